// round 9
// baseline (speedup 1.0000x reference)
#include <cuda_runtime.h>
#include <cuda_bf16.h>
#include <cuda_fp8.h>
#include <cstdint>

// ---------------------------------------------------------------------------
// Problem constants
// ---------------------------------------------------------------------------
#define NROWS 8192
#define DIM   2048
#define CS    8
#define NT    (NROWS / 128)            // 64 row-tiles of 128
#define NPAIR (NT * (NT + 1) / 2)      // 2080 symmetric tile pairs
#define BKB   128                      // 128 fp8 elements (=128 bytes) per K-step
#define KITER (DIM / BKB)              // 16
#define NSTAGE 3
#define STAGE_BYTES 16384              // 128 rows x 128 bytes
#define SMEM_BYTES (NSTAGE * STAGE_BYTES * 2)   // 98304: A stages then B stages

// Scratch (device globals; no allocations allowed)
__device__ uint8_t g_x8[(size_t)NROWS * DIM];         // fp8(e4m3) copy of x (16 MB)
__device__ float g_dap[NROWS];
__device__ unsigned long long g_best[NROWS];          // packed (mono(f32)<<32) | ~idx

// ---------------------------------------------------------------------------
// helpers
// ---------------------------------------------------------------------------
__device__ __forceinline__ void cp16(uint32_t dst, const void* src) {
    asm volatile("cp.async.cg.shared.global [%0], [%1], 16;\n" :: "r"(dst), "l"(src));
}
__device__ __forceinline__ void ldsm4(uint32_t& r0, uint32_t& r1, uint32_t& r2, uint32_t& r3,
                                      uint32_t a) {
    asm volatile("ldmatrix.sync.aligned.m8n8.x4.shared.b16 {%0,%1,%2,%3}, [%4];"
                 : "=r"(r0), "=r"(r1), "=r"(r2), "=r"(r3) : "r"(a));
}
__device__ __forceinline__ uint32_t smem_u32(const void* p) {
    uint32_t a;
    asm("{ .reg .u64 t; cvta.to.shared.u64 t, %1; cvt.u32.u64 %0, t; }" : "=r"(a) : "l"(p));
    return a;
}
__device__ __forceinline__ unsigned long long packmax(float v, int idx) {
    unsigned fb = __float_as_uint(v);
    unsigned mono = (fb & 0x80000000u) ? ~fb : (fb | 0x80000000u);
    return ((unsigned long long)mono << 32) | (unsigned)(~idx);
}
__device__ __forceinline__ unsigned long long umax64(unsigned long long a, unsigned long long b) {
    return a > b ? a : b;
}

// ---------------------------------------------------------------------------
// Kernel 1: chunk centers -> d_ap, fp32 -> fp8(e4m3) conversion, and
// per-row g_best/out reset (single pass; init kernel folded in)
// ---------------------------------------------------------------------------
__global__ void prep_kernel(const float* __restrict__ x, float* out) {
    const int r0 = blockIdx.x * CS;
    float acc[CS];
#pragma unroll
    for (int k = 0; k < CS; k++) acc[k] = 0.0f;

    if (threadIdx.x < CS) g_best[r0 + threadIdx.x] = 0ULL;
    if (blockIdx.x == 0 && threadIdx.x == 0) out[0] = 0.0f;

    for (int d = threadIdx.x; d < DIM / 4; d += 256) {
        float4 v[CS];
        float4 s = make_float4(0.f, 0.f, 0.f, 0.f);
#pragma unroll
        for (int k = 0; k < CS; k++) {
            v[k] = reinterpret_cast<const float4*>(x + (size_t)(r0 + k) * DIM)[d];
            s.x += v[k].x; s.y += v[k].y; s.z += v[k].z; s.w += v[k].w;
        }
        const float4 c = make_float4(s.x * 0.125f, s.y * 0.125f, s.z * 0.125f, s.w * 0.125f);
#pragma unroll
        for (int k = 0; k < CS; k++) {
            acc[k] += fabsf(v[k].x - c.x) + fabsf(v[k].y - c.y)
                    + fabsf(v[k].z - c.z) + fabsf(v[k].w - c.w);
            __nv_fp8x4_e4m3 p(v[k]);
            *reinterpret_cast<uint32_t*>(&g_x8[(size_t)(r0 + k) * DIM + d * 4]) =
                *reinterpret_cast<uint32_t*>(&p);
        }
    }

    __shared__ float sred[CS];
    if (threadIdx.x < CS) sred[threadIdx.x] = 0.0f;
    __syncthreads();
#pragma unroll
    for (int k = 0; k < CS; k++)
#pragma unroll
        for (int o = 16; o > 0; o >>= 1)
            acc[k] += __shfl_xor_sync(0xFFFFFFFFu, acc[k], o);
    if ((threadIdx.x & 31) == 0)
#pragma unroll
        for (int k = 0; k < CS; k++) atomicAdd(&sred[k], acc[k]);
    __syncthreads();
    if (threadIdx.x < CS)
        g_dap[r0 + threadIdx.x] = 0.5f * sred[threadIdx.x] / (float)DIM;
}

// ---------------------------------------------------------------------------
// Kernel 2: symmetric sim-GEMM (mma.sync fp8 e4m3 m16n8k32), 128x128 tile
// pairs ti<=tj, 3-stage cp.async pipeline, SW128 swizzle + ldmatrix, fused
// row-argmax (rows i) + col-argmax (cols j) epilogue.
// grid = NPAIR, block = 256 (8 warps: 2(M) x 4(N), each 64x32)
// NOTE: fp8 m16n8k32 per-lane fragment byte offsets are identical to
// bf16 m16n8k16 (4B per lane per 16B k-chunk, +16B k-half), so all
// ldmatrix addressing carries over unchanged.
// ---------------------------------------------------------------------------
__global__ __launch_bounds__(256, 2) void simgemm_kernel() {
    extern __shared__ char smem[];
    __shared__ unsigned long long rowbest_s[128];
    __shared__ unsigned long long colbest_s[128];

    const uint32_t sb = smem_u32(smem);
    const int tid  = threadIdx.x;
    const int lane = tid & 31;
    const int warp = tid >> 5;
    const int wr   = warp >> 2;        // 0..1 -> M offset wr*64
    const int wc   = warp & 3;         // 0..3 -> N offset wc*32
    const int qr   = lane >> 2;        // 0..7
    const int qc   = (lane & 3) * 2;   // 0,2,4,6

    // pair decode: blockIdx.x -> (ti, tj), ti <= tj
    int t = blockIdx.x, ti = 0, len = NT;
    while (t >= len) { t -= len; len--; ti++; }
    const int tj = ti + t;
    const bool diag = (ti == tj);
    const int i0 = ti * 128, j0 = tj * 128;

    if (tid < 128) { rowbest_s[tid] = 0ULL; colbest_s[tid] = 0ULL; }

    const uint8_t* gA = g_x8 + (size_t)i0 * DIM;
    const uint8_t* gB = g_x8 + (size_t)j0 * DIM;
    const uint32_t sB_read = diag ? sb : (sb + NSTAGE * STAGE_BYTES);

    // ---- prologue: fill stages 0,1 ----
#pragma unroll
    for (int st = 0; st < NSTAGE - 1; st++) {
        const int k0 = st * BKB;
        const uint32_t aBase = sb + st * STAGE_BYTES;
        const uint32_t bBase = sb + NSTAGE * STAGE_BYTES + st * STAGE_BYTES;
#pragma unroll
        for (int v = 0; v < 4; v++) {
            const int idx = tid + v * 256;
            const int row = idx >> 3;
            const int cb  = (idx & 7) * 16;                // byte (=elem) col
            const uint32_t off = row * 128 + cb;
            const uint32_t sw  = off ^ ((off >> 3) & 0x70);
            cp16(aBase + sw, gA + (size_t)row * DIM + k0 + cb);
            if (!diag) cp16(bBase + sw, gB + (size_t)row * DIM + k0 + cb);
        }
        asm volatile("cp.async.commit_group;\n");
    }

    float acc[4][4][4];
#pragma unroll
    for (int mt = 0; mt < 4; mt++)
#pragma unroll
        for (int nt = 0; nt < 4; nt++)
#pragma unroll
            for (int e = 0; e < 4; e++) acc[mt][nt][e] = 0.0f;

    // per-lane ldmatrix addressing constants (identical to bf16 layout)
    const int am    = wr * 64 + (lane & 15);               // A row for this lane
    const uint32_t aRow = (uint32_t)am * 128;
    const uint32_t aXor = (uint32_t)((am & 7) << 4);
    const uint32_t aKh  = (uint32_t)((lane >> 4) * 16);    // k-half byte offset
    const int bn    = wc * 32 + (lane & 7) + ((lane >> 4) << 3);  // B (n) row
    const uint32_t bRow = (uint32_t)bn * 128;
    const uint32_t bXor = (uint32_t)((bn & 7) << 4);
    const uint32_t bKh  = (uint32_t)(((lane >> 3) & 1) * 16);

    // ---- mainloop ----
    for (int kk = 0; kk < KITER; kk++) {
        asm volatile("cp.async.wait_group 1;\n");
        __syncthreads();

        // prefetch stage kk+2 (always commit to keep group numbering)
        {
            const int f = kk + NSTAGE - 1;
            if (f < KITER) {
                const int s = f % NSTAGE;
                const int k0 = f * BKB;
                const uint32_t aBase = sb + s * STAGE_BYTES;
                const uint32_t bBase = sb + NSTAGE * STAGE_BYTES + s * STAGE_BYTES;
#pragma unroll
                for (int v = 0; v < 4; v++) {
                    const int idx = tid + v * 256;
                    const int row = idx >> 3;
                    const int cb  = (idx & 7) * 16;
                    const uint32_t off = row * 128 + cb;
                    const uint32_t sw  = off ^ ((off >> 3) & 0x70);
                    cp16(aBase + sw, gA + (size_t)row * DIM + k0 + cb);
                    if (!diag) cp16(bBase + sw, gB + (size_t)row * DIM + k0 + cb);
                }
            }
            asm volatile("cp.async.commit_group;\n");
        }

        const int s = kk % NSTAGE;
        const uint32_t aT = sb + s * STAGE_BYTES;
        const uint32_t bT = sB_read + s * STAGE_BYTES;

#pragma unroll
        for (int ks = 0; ks < 4; ks++) {
            const uint32_t kb = (uint32_t)(ks * 32);       // byte offset of k32 step
            uint32_t af[4][4], bf[4][2];
#pragma unroll
            for (int mt = 0; mt < 4; mt++) {
                const uint32_t addr = aT + aRow + (uint32_t)(mt * 2048)
                                    + ((kb + aKh) ^ aXor);
                ldsm4(af[mt][0], af[mt][1], af[mt][2], af[mt][3], addr);
            }
#pragma unroll
            for (int np = 0; np < 2; np++) {
                const uint32_t addr = bT + bRow + (uint32_t)(np * 2048)
                                    + ((kb + bKh) ^ bXor);
                ldsm4(bf[np * 2][0], bf[np * 2][1], bf[np * 2 + 1][0], bf[np * 2 + 1][1], addr);
            }
#pragma unroll
            for (int mt = 0; mt < 4; mt++)
#pragma unroll
                for (int nt = 0; nt < 4; nt++) {
                    asm volatile(
                        "mma.sync.aligned.m16n8k32.row.col.f32.e4m3.e4m3.f32 "
                        "{%0,%1,%2,%3}, {%4,%5,%6,%7}, {%8,%9}, {%0,%1,%2,%3};\n"
                        : "+f"(acc[mt][nt][0]), "+f"(acc[mt][nt][1]),
                          "+f"(acc[mt][nt][2]), "+f"(acc[mt][nt][3])
                        : "r"(af[mt][0]), "r"(af[mt][1]),
                          "r"(af[mt][2]), "r"(af[mt][3]),
                          "r"(bf[nt][0]), "r"(bf[nt][1]));
                }
        }
    }

    // ---- epilogue ----
    // row-argmax (rows i0..i0+127 over cols j0..j0+127)
#pragma unroll
    for (int mt = 0; mt < 4; mt++) {
#pragma unroll
        for (int h = 0; h < 2; h++) {
            const int mrow = wr * 64 + mt * 16 + qr + 8 * h;
            unsigned long long b = 0ULL;
            if (diag) {
                const int igrp = (i0 + mrow) >> 2;
#pragma unroll
                for (int nt = 0; nt < 4; nt++)
#pragma unroll
                    for (int c = 0; c < 2; c++) {
                        const int jg = j0 + wc * 32 + nt * 8 + qc + c;
                        if ((jg >> 2) != igrp)
                            b = umax64(b, packmax(acc[mt][nt][h * 2 + c], jg));
                    }
            } else {
#pragma unroll
                for (int nt = 0; nt < 4; nt++)
#pragma unroll
                    for (int c = 0; c < 2; c++) {
                        const int jg = j0 + wc * 32 + nt * 8 + qc + c;
                        b = umax64(b, packmax(acc[mt][nt][h * 2 + c], jg));
                    }
            }
            b = umax64(b, __shfl_xor_sync(0xFFFFFFFFu, b, 1));
            b = umax64(b, __shfl_xor_sync(0xFFFFFFFFu, b, 2));
            if ((lane & 3) == 0) atomicMax(&rowbest_s[mrow], b);
        }
    }

    // col-argmax (cols j0..j0+127 over rows i0..i0+127); sim[j][i] by symmetry.
    if (!diag) {
#pragma unroll
        for (int nt = 0; nt < 4; nt++) {
#pragma unroll
            for (int c = 0; c < 2; c++) {
                unsigned long long b = 0ULL;
#pragma unroll
                for (int mt = 0; mt < 4; mt++)
#pragma unroll
                    for (int h = 0; h < 2; h++) {
                        const int ig = i0 + wr * 64 + mt * 16 + qr + 8 * h;
                        b = umax64(b, packmax(acc[mt][nt][h * 2 + c], ig));
                    }
                b = umax64(b, __shfl_xor_sync(0xFFFFFFFFu, b, 4));
                b = umax64(b, __shfl_xor_sync(0xFFFFFFFFu, b, 8));
                b = umax64(b, __shfl_xor_sync(0xFFFFFFFFu, b, 16));
                if (lane < 4)
                    atomicMax(&colbest_s[wc * 32 + nt * 8 + qc + c], b);
            }
        }
    }
    __syncthreads();
    if (tid < 128) {
        atomicMax(&g_best[i0 + tid], rowbest_s[tid]);
        if (!diag) atomicMax(&g_best[j0 + tid], colbest_s[tid]);
    }
}

// ---------------------------------------------------------------------------
// Kernel 3: d_an gather + weighted ratio sum (float4 vectorized, exact fp32)
// ---------------------------------------------------------------------------
__global__ void finalize_kernel(const float* __restrict__ x, float* out) {
    const int i = blockIdx.x;
    const unsigned jg = ~(unsigned)(g_best[i] & 0xFFFFFFFFULL);
    const float4* xi = reinterpret_cast<const float4*>(x + (size_t)i * DIM);
    const float4* xj = reinterpret_cast<const float4*>(x + (size_t)jg * DIM);

    float s = 0.0f;
    for (int d = threadIdx.x; d < DIM / 4; d += 256) {
        const float4 a = xi[d], b = xj[d];
        s += fabsf(a.x - b.x) + fabsf(a.y - b.y) + fabsf(a.z - b.z) + fabsf(a.w - b.w);
    }
#pragma unroll
    for (int o = 16; o > 0; o >>= 1)
        s += __shfl_xor_sync(0xFFFFFFFFu, s, o);

    __shared__ float sw[8];
    if ((threadIdx.x & 31) == 0) sw[threadIdx.x >> 5] = s;
    __syncthreads();
    if (threadIdx.x == 0) {
        float tot = 0.0f;
#pragma unroll
        for (int w = 0; w < 8; w++) tot += sw[w];
        const float dan = tot / (float)DIM;
        atomicAdd(out, 0.125f * g_dap[i] / (dan + 1e-7f));
    }
}

// ---------------------------------------------------------------------------
extern "C" void kernel_launch(void* const* d_in, const int* in_sizes, int n_in,
                              void* d_out, int out_size) {
    const float* x = (const float*)d_in[0];
    float* out = (float*)d_out;

    static bool attr_set = false;
    if (!attr_set) {
        cudaFuncSetAttribute(simgemm_kernel,
                             cudaFuncAttributeMaxDynamicSharedMemorySize, SMEM_BYTES);
        attr_set = true;
    }

    prep_kernel<<<NROWS / CS, 256>>>(x, out);
    simgemm_kernel<<<NPAIR, 256, SMEM_BYTES>>>();
    finalize_kernel<<<NROWS, 256>>>(x, out);
}

// round 10
// speedup vs baseline: 1.0521x; 1.0521x over previous
#include <cuda_runtime.h>
#include <cuda_fp16.h>
#include <cstdint>

// ---------------------------------------------------------------------------
// Problem constants
// ---------------------------------------------------------------------------
#define NROWS 8192
#define DIM   2048
#define CS    8
#define NT    (NROWS / 128)            // 64 row-tiles of 128
#define NPAIR (NT * (NT + 1) / 2)      // 2080 symmetric tile pairs
#define BK    64
#define KITER (DIM / BK)               // 32
#define NSTAGE 3
#define STAGE_BYTES 16384              // 128 rows x 128 bytes (64 f16)
#define SMEM_BYTES (NSTAGE * STAGE_BYTES * 2)   // 98304: A stages then B stages

// Scratch (device globals; no allocations allowed)
__device__ __half g_xh[(size_t)NROWS * DIM];          // f16 copy of x (32 MB)
__device__ float g_dap[NROWS];
__device__ unsigned long long g_best[NROWS];          // packed (mono(f32)<<32) | ~idx

// ---------------------------------------------------------------------------
// helpers
// ---------------------------------------------------------------------------
__device__ __forceinline__ void cp16(uint32_t dst, const void* src) {
    asm volatile("cp.async.cg.shared.global [%0], [%1], 16;\n" :: "r"(dst), "l"(src));
}
__device__ __forceinline__ void ldsm4(uint32_t& r0, uint32_t& r1, uint32_t& r2, uint32_t& r3,
                                      uint32_t a) {
    asm volatile("ldmatrix.sync.aligned.m8n8.x4.shared.b16 {%0,%1,%2,%3}, [%4];"
                 : "=r"(r0), "=r"(r1), "=r"(r2), "=r"(r3) : "r"(a));
}
__device__ __forceinline__ uint32_t smem_u32(const void* p) {
    uint32_t a;
    asm("{ .reg .u64 t; cvta.to.shared.u64 t, %1; cvt.u32.u64 %0, t; }" : "=r"(a) : "l"(p));
    return a;
}
__device__ __forceinline__ unsigned long long packmax(float v, int idx) {
    unsigned fb = __float_as_uint(v);
    unsigned mono = (fb & 0x80000000u) ? ~fb : (fb | 0x80000000u);
    return ((unsigned long long)mono << 32) | (unsigned)(~idx);
}
__device__ __forceinline__ unsigned long long umax64(unsigned long long a, unsigned long long b) {
    return a > b ? a : b;
}

// ---------------------------------------------------------------------------
// Kernel 1: chunk centers -> d_ap, fp32 -> f16 conversion, g_best/out reset
// ---------------------------------------------------------------------------
__global__ void prep_kernel(const float* __restrict__ x, float* out) {
    const int r0 = blockIdx.x * CS;
    float acc[CS];
#pragma unroll
    for (int k = 0; k < CS; k++) acc[k] = 0.0f;

    if (threadIdx.x < CS) g_best[r0 + threadIdx.x] = 0ULL;
    if (blockIdx.x == 0 && threadIdx.x == 0) out[0] = 0.0f;

    for (int d = threadIdx.x; d < DIM / 4; d += 256) {
        float4 v[CS];
        float4 s = make_float4(0.f, 0.f, 0.f, 0.f);
#pragma unroll
        for (int k = 0; k < CS; k++) {
            v[k] = reinterpret_cast<const float4*>(x + (size_t)(r0 + k) * DIM)[d];
            s.x += v[k].x; s.y += v[k].y; s.z += v[k].z; s.w += v[k].w;
        }
        const float4 c = make_float4(s.x * 0.125f, s.y * 0.125f, s.z * 0.125f, s.w * 0.125f);
#pragma unroll
        for (int k = 0; k < CS; k++) {
            acc[k] += fabsf(v[k].x - c.x) + fabsf(v[k].y - c.y)
                    + fabsf(v[k].z - c.z) + fabsf(v[k].w - c.w);
            __half2 lo = __floats2half2_rn(v[k].x, v[k].y);
            __half2 hi = __floats2half2_rn(v[k].z, v[k].w);
            uint2 u;
            u.x = *reinterpret_cast<unsigned*>(&lo);
            u.y = *reinterpret_cast<unsigned*>(&hi);
            *reinterpret_cast<uint2*>(&g_xh[(size_t)(r0 + k) * DIM + d * 4]) = u;
        }
    }

    __shared__ float sred[CS];
    if (threadIdx.x < CS) sred[threadIdx.x] = 0.0f;
    __syncthreads();
#pragma unroll
    for (int k = 0; k < CS; k++)
#pragma unroll
        for (int o = 16; o > 0; o >>= 1)
            acc[k] += __shfl_xor_sync(0xFFFFFFFFu, acc[k], o);
    if ((threadIdx.x & 31) == 0)
#pragma unroll
        for (int k = 0; k < CS; k++) atomicAdd(&sred[k], acc[k]);
    __syncthreads();
    if (threadIdx.x < CS)
        g_dap[r0 + threadIdx.x] = 0.5f * sred[threadIdx.x] / (float)DIM;
}

// ---------------------------------------------------------------------------
// Kernel 2: symmetric sim-GEMM (mma.sync f16 inputs, f16 accumulators),
// 128x128 tile pairs ti<=tj, 3-stage cp.async pipeline, SW128 swizzle +
// ldmatrix, fused row-argmax + col-argmax epilogue.
// grid = NPAIR, block = 256 (8 warps: 2(M) x 4(N), each 64x32)
// ---------------------------------------------------------------------------
__global__ __launch_bounds__(256, 2) void simgemm_kernel() {
    extern __shared__ char smem[];
    __shared__ unsigned long long rowbest_s[128];
    __shared__ unsigned long long colbest_s[128];

    const uint32_t sb = smem_u32(smem);
    const int tid  = threadIdx.x;
    const int lane = tid & 31;
    const int warp = tid >> 5;
    const int wr   = warp >> 2;        // 0..1 -> M offset wr*64
    const int wc   = warp & 3;         // 0..3 -> N offset wc*32
    const int qr   = lane >> 2;        // 0..7
    const int qc   = (lane & 3) * 2;   // 0,2,4,6

    // pair decode: blockIdx.x -> (ti, tj), ti <= tj
    int t = blockIdx.x, ti = 0, len = NT;
    while (t >= len) { t -= len; len--; ti++; }
    const int tj = ti + t;
    const bool diag = (ti == tj);
    const int i0 = ti * 128, j0 = tj * 128;

    if (tid < 128) { rowbest_s[tid] = 0ULL; colbest_s[tid] = 0ULL; }

    const __half* gA = g_xh + (size_t)i0 * DIM;
    const __half* gB = g_xh + (size_t)j0 * DIM;
    const uint32_t sB_read = diag ? sb : (sb + NSTAGE * STAGE_BYTES);

    // ---- prologue: fill stages 0,1 ----
#pragma unroll
    for (int st = 0; st < NSTAGE - 1; st++) {
        const int k0 = st * BK;
        const uint32_t aBase = sb + st * STAGE_BYTES;
        const uint32_t bBase = sb + NSTAGE * STAGE_BYTES + st * STAGE_BYTES;
#pragma unroll
        for (int v = 0; v < 4; v++) {
            const int idx = tid + v * 256;
            const int row = idx >> 3;
            const int c8  = (idx & 7) * 8;                 // element col
            const uint32_t off = row * 128 + c8 * 2;
            const uint32_t sw  = off ^ ((off >> 3) & 0x70);
            cp16(aBase + sw, gA + (size_t)row * DIM + k0 + c8);
            if (!diag) cp16(bBase + sw, gB + (size_t)row * DIM + k0 + c8);
        }
        asm volatile("cp.async.commit_group;\n");
    }

    // f16 accumulators: 2 regs (4 halves) per 16x8 tile
    uint32_t acc[4][4][2];
#pragma unroll
    for (int mt = 0; mt < 4; mt++)
#pragma unroll
        for (int nt = 0; nt < 4; nt++) { acc[mt][nt][0] = 0u; acc[mt][nt][1] = 0u; }

    // per-lane ldmatrix addressing constants
    const int am    = wr * 64 + (lane & 15);               // A row for this lane
    const uint32_t aRow = (uint32_t)am * 128;
    const uint32_t aXor = (uint32_t)((am & 7) << 4);
    const uint32_t aKh  = (uint32_t)((lane >> 4) * 16);    // k-half byte offset
    const int bn    = wc * 32 + (lane & 7) + ((lane >> 4) << 3);  // B (n) row
    const uint32_t bRow = (uint32_t)bn * 128;
    const uint32_t bXor = (uint32_t)((bn & 7) << 4);
    const uint32_t bKh  = (uint32_t)(((lane >> 3) & 1) * 16);

    // ---- mainloop ----
    for (int kk = 0; kk < KITER; kk++) {
        asm volatile("cp.async.wait_group 1;\n");
        __syncthreads();

        // prefetch stage kk+2 (always commit to keep group numbering)
        {
            const int f = kk + NSTAGE - 1;
            if (f < KITER) {
                const int s = f % NSTAGE;
                const int k0 = f * BK;
                const uint32_t aBase = sb + s * STAGE_BYTES;
                const uint32_t bBase = sb + NSTAGE * STAGE_BYTES + s * STAGE_BYTES;
#pragma unroll
                for (int v = 0; v < 4; v++) {
                    const int idx = tid + v * 256;
                    const int row = idx >> 3;
                    const int c8  = (idx & 7) * 8;
                    const uint32_t off = row * 128 + c8 * 2;
                    const uint32_t sw  = off ^ ((off >> 3) & 0x70);
                    cp16(aBase + sw, gA + (size_t)row * DIM + k0 + c8);
                    if (!diag) cp16(bBase + sw, gB + (size_t)row * DIM + k0 + c8);
                }
            }
            asm volatile("cp.async.commit_group;\n");
        }

        const int s = kk % NSTAGE;
        const uint32_t aT = sb + s * STAGE_BYTES;
        const uint32_t bT = sB_read + s * STAGE_BYTES;

#pragma unroll
        for (int ks = 0; ks < 4; ks++) {
            const uint32_t kb = (uint32_t)(ks * 32);       // byte offset of k-step
            uint32_t af[4][4], bf[4][2];
#pragma unroll
            for (int mt = 0; mt < 4; mt++) {
                const uint32_t addr = aT + aRow + (uint32_t)(mt * 2048)
                                    + ((kb + aKh) ^ aXor);
                ldsm4(af[mt][0], af[mt][1], af[mt][2], af[mt][3], addr);
            }
#pragma unroll
            for (int np = 0; np < 2; np++) {
                const uint32_t addr = bT + bRow + (uint32_t)(np * 2048)
                                    + ((kb + bKh) ^ bXor);
                ldsm4(bf[np * 2][0], bf[np * 2][1], bf[np * 2 + 1][0], bf[np * 2 + 1][1], addr);
            }
#pragma unroll
            for (int mt = 0; mt < 4; mt++)
#pragma unroll
                for (int nt = 0; nt < 4; nt++) {
                    asm volatile(
                        "mma.sync.aligned.m16n8k16.row.col.f16.f16.f16.f16 "
                        "{%0,%1}, {%2,%3,%4,%5}, {%6,%7}, {%0,%1};\n"
                        : "+r"(acc[mt][nt][0]), "+r"(acc[mt][nt][1])
                        : "r"(af[mt][0]), "r"(af[mt][1]),
                          "r"(af[mt][2]), "r"(af[mt][3]),
                          "r"(bf[nt][0]), "r"(bf[nt][1]));
                }
        }
    }

    // unpack f16 accumulators to f32 per-element view:
    // reg0 = {row qr,   col qc}, {row qr,   col qc+1}
    // reg1 = {row qr+8, col qc}, {row qr+8, col qc+1}
    float accf[4][4][4];
#pragma unroll
    for (int mt = 0; mt < 4; mt++)
#pragma unroll
        for (int nt = 0; nt < 4; nt++) {
            const float2 p0 = __half22float2(*reinterpret_cast<__half2*>(&acc[mt][nt][0]));
            const float2 p1 = __half22float2(*reinterpret_cast<__half2*>(&acc[mt][nt][1]));
            accf[mt][nt][0] = p0.x;   // h=0, c=0
            accf[mt][nt][1] = p0.y;   // h=0, c=1
            accf[mt][nt][2] = p1.x;   // h=1, c=0
            accf[mt][nt][3] = p1.y;   // h=1, c=1
        }

    // ---- epilogue ----
    // row-argmax (rows i0..i0+127 over cols j0..j0+127)
#pragma unroll
    for (int mt = 0; mt < 4; mt++) {
#pragma unroll
        for (int h = 0; h < 2; h++) {
            const int mrow = wr * 64 + mt * 16 + qr + 8 * h;
            unsigned long long b = 0ULL;
            if (diag) {
                const int igrp = (i0 + mrow) >> 2;
#pragma unroll
                for (int nt = 0; nt < 4; nt++)
#pragma unroll
                    for (int c = 0; c < 2; c++) {
                        const int jg = j0 + wc * 32 + nt * 8 + qc + c;
                        if ((jg >> 2) != igrp)
                            b = umax64(b, packmax(accf[mt][nt][h * 2 + c], jg));
                    }
            } else {
#pragma unroll
                for (int nt = 0; nt < 4; nt++)
#pragma unroll
                    for (int c = 0; c < 2; c++) {
                        const int jg = j0 + wc * 32 + nt * 8 + qc + c;
                        b = umax64(b, packmax(accf[mt][nt][h * 2 + c], jg));
                    }
            }
            b = umax64(b, __shfl_xor_sync(0xFFFFFFFFu, b, 1));
            b = umax64(b, __shfl_xor_sync(0xFFFFFFFFu, b, 2));
            if ((lane & 3) == 0) atomicMax(&rowbest_s[mrow], b);
        }
    }

    // col-argmax (cols j0..j0+127 over rows i0..i0+127); sim[j][i] by symmetry.
    if (!diag) {
#pragma unroll
        for (int nt = 0; nt < 4; nt++) {
#pragma unroll
            for (int c = 0; c < 2; c++) {
                unsigned long long b = 0ULL;
#pragma unroll
                for (int mt = 0; mt < 4; mt++)
#pragma unroll
                    for (int h = 0; h < 2; h++) {
                        const int ig = i0 + wr * 64 + mt * 16 + qr + 8 * h;
                        b = umax64(b, packmax(accf[mt][nt][h * 2 + c], ig));
                    }
                b = umax64(b, __shfl_xor_sync(0xFFFFFFFFu, b, 4));
                b = umax64(b, __shfl_xor_sync(0xFFFFFFFFu, b, 8));
                b = umax64(b, __shfl_xor_sync(0xFFFFFFFFu, b, 16));
                if (lane < 4)
                    atomicMax(&colbest_s[wc * 32 + nt * 8 + qc + c], b);
            }
        }
    }
    __syncthreads();
    if (tid < 128) {
        atomicMax(&g_best[i0 + tid], rowbest_s[tid]);
        if (!diag) atomicMax(&g_best[j0 + tid], colbest_s[tid]);
    }
}

// ---------------------------------------------------------------------------
// Kernel 3: d_an gather + weighted ratio sum (float4 vectorized, exact fp32)
// ---------------------------------------------------------------------------
__global__ void finalize_kernel(const float* __restrict__ x, float* out) {
    const int i = blockIdx.x;
    const unsigned jg = ~(unsigned)(g_best[i] & 0xFFFFFFFFULL);
    const float4* xi = reinterpret_cast<const float4*>(x + (size_t)i * DIM);
    const float4* xj = reinterpret_cast<const float4*>(x + (size_t)jg * DIM);

    float s = 0.0f;
    for (int d = threadIdx.x; d < DIM / 4; d += 256) {
        const float4 a = xi[d], b = xj[d];
        s += fabsf(a.x - b.x) + fabsf(a.y - b.y) + fabsf(a.z - b.z) + fabsf(a.w - b.w);
    }
#pragma unroll
    for (int o = 16; o > 0; o >>= 1)
        s += __shfl_xor_sync(0xFFFFFFFFu, s, o);

    __shared__ float sw[8];
    if ((threadIdx.x & 31) == 0) sw[threadIdx.x >> 5] = s;
    __syncthreads();
    if (threadIdx.x == 0) {
        float tot = 0.0f;
#pragma unroll
        for (int w = 0; w < 8; w++) tot += sw[w];
        const float dan = tot / (float)DIM;
        atomicAdd(out, 0.125f * g_dap[i] / (dan + 1e-7f));
    }
}

// ---------------------------------------------------------------------------
extern "C" void kernel_launch(void* const* d_in, const int* in_sizes, int n_in,
                              void* d_out, int out_size) {
    const float* x = (const float*)d_in[0];
    float* out = (float*)d_out;

    static bool attr_set = false;
    if (!attr_set) {
        cudaFuncSetAttribute(simgemm_kernel,
                             cudaFuncAttributeMaxDynamicSharedMemorySize, SMEM_BYTES);
        attr_set = true;
    }

    prep_kernel<<<NROWS / CS, 256>>>(x, out);
    simgemm_kernel<<<NPAIR, 256, SMEM_BYTES>>>();
    finalize_kernel<<<NROWS, 256>>>(x, out);
}

// round 12
// speedup vs baseline: 1.1617x; 1.1041x over previous
#include <cuda_runtime.h>
#include <cuda_fp16.h>
#include <cstdint>

// ---------------------------------------------------------------------------
// Problem constants
// ---------------------------------------------------------------------------
#define NROWS 8192
#define DIM   2048
#define CS    8
#define NT    (NROWS / 128)            // 64 row-tiles of 128
#define NPAIR (NT * (NT + 1) / 2)      // 2080 symmetric tile pairs
#define BK    64
#define KITER (DIM / BK)               // 32
#define NSTAGE 2
#define STAGE_BYTES 16384              // 128 rows x 128 bytes (64 f16)
#define SMEM_BYTES (NSTAGE * STAGE_BYTES * 2)   // 65536: A stages then B stages

// Scratch (device globals; no allocations allowed)
__device__ __half g_xh[(size_t)NROWS * DIM];          // f16 copy of x (32 MB)
__device__ float g_dap[NROWS];
__device__ unsigned long long g_best[NROWS];          // packed (mono(f32)<<32) | ~idx

// ---------------------------------------------------------------------------
// helpers
// ---------------------------------------------------------------------------
__device__ __forceinline__ void cp16(uint32_t dst, const void* src) {
    asm volatile("cp.async.cg.shared.global [%0], [%1], 16;\n" :: "r"(dst), "l"(src));
}
__device__ __forceinline__ void ldsm4(uint32_t& r0, uint32_t& r1, uint32_t& r2, uint32_t& r3,
                                      uint32_t a) {
    asm volatile("ldmatrix.sync.aligned.m8n8.x4.shared.b16 {%0,%1,%2,%3}, [%4];"
                 : "=r"(r0), "=r"(r1), "=r"(r2), "=r"(r3) : "r"(a));
}
__device__ __forceinline__ uint32_t smem_u32(const void* p) {
    uint32_t a;
    asm("{ .reg .u64 t; cvta.to.shared.u64 t, %1; cvt.u32.u64 %0, t; }" : "=r"(a) : "l"(p));
    return a;
}
__device__ __forceinline__ unsigned long long packmax(float v, int idx) {
    unsigned fb = __float_as_uint(v);
    unsigned mono = (fb & 0x80000000u) ? ~fb : (fb | 0x80000000u);
    return ((unsigned long long)mono << 32) | (unsigned)(~idx);
}
__device__ __forceinline__ unsigned long long umax64(unsigned long long a, unsigned long long b) {
    return a > b ? a : b;
}

// ---------------------------------------------------------------------------
// Kernel 1: chunk centers -> d_ap, fp32 -> f16 conversion, g_best/out reset
// 512 threads, loop-free (DIM/4 == 512)
// ---------------------------------------------------------------------------
__global__ __launch_bounds__(512) void prep_kernel(const float* __restrict__ x, float* out) {
    const int r0 = blockIdx.x * CS;
    const int d  = threadIdx.x;                    // 0..511 == DIM/4 columns

    if (threadIdx.x < CS) g_best[r0 + threadIdx.x] = 0ULL;
    if (blockIdx.x == 0 && threadIdx.x == 0) out[0] = 0.0f;

    float acc[CS];
    float4 v[CS];
    float4 s = make_float4(0.f, 0.f, 0.f, 0.f);
#pragma unroll
    for (int k = 0; k < CS; k++) {
        v[k] = reinterpret_cast<const float4*>(x + (size_t)(r0 + k) * DIM)[d];
        s.x += v[k].x; s.y += v[k].y; s.z += v[k].z; s.w += v[k].w;
    }
    const float4 c = make_float4(s.x * 0.125f, s.y * 0.125f, s.z * 0.125f, s.w * 0.125f);
#pragma unroll
    for (int k = 0; k < CS; k++) {
        acc[k] = fabsf(v[k].x - c.x) + fabsf(v[k].y - c.y)
               + fabsf(v[k].z - c.z) + fabsf(v[k].w - c.w);
        __half2 lo = __floats2half2_rn(v[k].x, v[k].y);
        __half2 hi = __floats2half2_rn(v[k].z, v[k].w);
        uint2 u;
        u.x = *reinterpret_cast<unsigned*>(&lo);
        u.y = *reinterpret_cast<unsigned*>(&hi);
        *reinterpret_cast<uint2*>(&g_xh[(size_t)(r0 + k) * DIM + d * 4]) = u;
    }

    __shared__ float sred[CS];
    if (threadIdx.x < CS) sred[threadIdx.x] = 0.0f;
    __syncthreads();
#pragma unroll
    for (int k = 0; k < CS; k++)
#pragma unroll
        for (int o = 16; o > 0; o >>= 1)
            acc[k] += __shfl_xor_sync(0xFFFFFFFFu, acc[k], o);
    if ((threadIdx.x & 31) == 0)
#pragma unroll
        for (int k = 0; k < CS; k++) atomicAdd(&sred[k], acc[k]);
    __syncthreads();
    if (threadIdx.x < CS)
        g_dap[r0 + threadIdx.x] = 0.5f * sred[threadIdx.x] / (float)DIM;
}

// ---------------------------------------------------------------------------
// Kernel 2: symmetric sim-GEMM (mma.sync f16 in, f16 acc), 128x128 tile pairs
// ti<=tj, 2-stage cp.async double buffer, SW128 swizzle + ldmatrix, fused
// row-argmax + col-argmax epilogue. 3 CTAs/SM.
// grid = NPAIR, block = 256 (8 warps: 2(M) x 4(N), each 64x32)
// ---------------------------------------------------------------------------
__global__ __launch_bounds__(256, 3) void simgemm_kernel() {
    extern __shared__ char smem[];
    __shared__ unsigned long long rowbest_s[128];
    __shared__ unsigned long long colbest_s[128];

    const uint32_t sb = smem_u32(smem);
    const int tid  = threadIdx.x;
    const int lane = tid & 31;
    const int warp = tid >> 5;
    const int wr   = warp >> 2;        // 0..1 -> M offset wr*64
    const int wc   = warp & 3;         // 0..3 -> N offset wc*32
    const int qr   = lane >> 2;        // 0..7
    const int qc   = (lane & 3) * 2;   // 0,2,4,6

    // pair decode: blockIdx.x -> (ti, tj), ti <= tj
    int t = blockIdx.x, ti = 0, len = NT;
    while (t >= len) { t -= len; len--; ti++; }
    const int tj = ti + t;
    const bool diag = (ti == tj);
    const int i0 = ti * 128, j0 = tj * 128;

    if (tid < 128) { rowbest_s[tid] = 0ULL; colbest_s[tid] = 0ULL; }

    const __half* gA = g_xh + (size_t)i0 * DIM;
    const __half* gB = g_xh + (size_t)j0 * DIM;
    const uint32_t sB_read = diag ? sb : (sb + NSTAGE * STAGE_BYTES);

    // ---- prologue: fill stage 0 ----
    {
#pragma unroll
        for (int v = 0; v < 4; v++) {
            const int idx = tid + v * 256;
            const int row = idx >> 3;
            const int c8  = (idx & 7) * 8;                 // element col
            const uint32_t off = row * 128 + c8 * 2;
            const uint32_t sw  = off ^ ((off >> 3) & 0x70);
            cp16(sb + sw, gA + (size_t)row * DIM + c8);
            if (!diag) cp16(sb + NSTAGE * STAGE_BYTES + sw,
                            gB + (size_t)row * DIM + c8);
        }
        asm volatile("cp.async.commit_group;\n");
    }

    // f16 accumulators: 2 regs (4 halves) per 16x8 tile
    uint32_t acc[4][4][2];
#pragma unroll
    for (int mt = 0; mt < 4; mt++)
#pragma unroll
        for (int nt = 0; nt < 4; nt++) { acc[mt][nt][0] = 0u; acc[mt][nt][1] = 0u; }

    // per-lane ldmatrix addressing constants
    const int am    = wr * 64 + (lane & 15);               // A row for this lane
    const uint32_t aRow = (uint32_t)am * 128;
    const uint32_t aXor = (uint32_t)((am & 7) << 4);
    const uint32_t aKh  = (uint32_t)((lane >> 4) * 16);    // k-half byte offset
    const int bn    = wc * 32 + (lane & 7) + ((lane >> 4) << 3);  // B (n) row
    const uint32_t bRow = (uint32_t)bn * 128;
    const uint32_t bXor = (uint32_t)((bn & 7) << 4);
    const uint32_t bKh  = (uint32_t)(((lane >> 3) & 1) * 16);

    // ---- mainloop: 2-stage double buffer, prefetch distance 1 ----
    for (int kk = 0; kk < KITER; kk++) {
        asm volatile("cp.async.wait_group 0;\n");   // stage kk%2 data complete
        __syncthreads();                            // visible to all; prev readers done

        // prefetch k-iter kk+1 into stage (kk+1)%2 (read last at iter kk-1)
        if (kk + 1 < KITER) {
            const int s = (kk + 1) & 1;
            const int k0 = (kk + 1) * BK;
            const uint32_t aBase = sb + s * STAGE_BYTES;
            const uint32_t bBase = sb + NSTAGE * STAGE_BYTES + s * STAGE_BYTES;
#pragma unroll
            for (int v = 0; v < 4; v++) {
                const int idx = tid + v * 256;
                const int row = idx >> 3;
                const int c8  = (idx & 7) * 8;
                const uint32_t off = row * 128 + c8 * 2;
                const uint32_t sw  = off ^ ((off >> 3) & 0x70);
                cp16(aBase + sw, gA + (size_t)row * DIM + k0 + c8);
                if (!diag) cp16(bBase + sw, gB + (size_t)row * DIM + k0 + c8);
            }
            asm volatile("cp.async.commit_group;\n");
        }

        const int s = kk & 1;
        const uint32_t aT = sb + s * STAGE_BYTES;
        const uint32_t bT = sB_read + s * STAGE_BYTES;

#pragma unroll
        for (int ks = 0; ks < 4; ks++) {
            const uint32_t kb = (uint32_t)(ks * 32);       // byte offset of k-step
            uint32_t af[4][4], bf[4][2];
#pragma unroll
            for (int mt = 0; mt < 4; mt++) {
                const uint32_t addr = aT + aRow + (uint32_t)(mt * 2048)
                                    + ((kb + aKh) ^ aXor);
                ldsm4(af[mt][0], af[mt][1], af[mt][2], af[mt][3], addr);
            }
#pragma unroll
            for (int np = 0; np < 2; np++) {
                const uint32_t addr = bT + bRow + (uint32_t)(np * 2048)
                                    + ((kb + bKh) ^ bXor);
                ldsm4(bf[np * 2][0], bf[np * 2][1], bf[np * 2 + 1][0], bf[np * 2 + 1][1], addr);
            }
#pragma unroll
            for (int mt = 0; mt < 4; mt++)
#pragma unroll
                for (int nt = 0; nt < 4; nt++) {
                    asm volatile(
                        "mma.sync.aligned.m16n8k16.row.col.f16.f16.f16.f16 "
                        "{%0,%1}, {%2,%3,%4,%5}, {%6,%7}, {%0,%1};\n"
                        : "+r"(acc[mt][nt][0]), "+r"(acc[mt][nt][1])
                        : "r"(af[mt][0]), "r"(af[mt][1]),
                          "r"(af[mt][2]), "r"(af[mt][3]),
                          "r"(bf[nt][0]), "r"(bf[nt][1]));
                }
        }
    }

    // ---- epilogue (unpack f16 acc on the fly) ----
    // acc reg h: {row qr+8h, col qc}, {row qr+8h, col qc+1}
    // row-argmax (rows i0..i0+127 over cols j0..j0+127)
#pragma unroll
    for (int mt = 0; mt < 4; mt++) {
#pragma unroll
        for (int h = 0; h < 2; h++) {
            const int mrow = wr * 64 + mt * 16 + qr + 8 * h;
            unsigned long long b = 0ULL;
            if (diag) {
                const int igrp = (i0 + mrow) >> 2;
#pragma unroll
                for (int nt = 0; nt < 4; nt++) {
                    const float2 p = __half22float2(
                        *reinterpret_cast<__half2*>(&acc[mt][nt][h]));
                    const int jg = j0 + wc * 32 + nt * 8 + qc;
                    if ((jg >> 2) != igrp) {           // qc,qc+1 same group of 4
                        b = umax64(b, packmax(p.x, jg));
                        b = umax64(b, packmax(p.y, jg + 1));
                    }
                }
            } else {
#pragma unroll
                for (int nt = 0; nt < 4; nt++) {
                    const float2 p = __half22float2(
                        *reinterpret_cast<__half2*>(&acc[mt][nt][h]));
                    const int jg = j0 + wc * 32 + nt * 8 + qc;
                    b = umax64(b, packmax(p.x, jg));
                    b = umax64(b, packmax(p.y, jg + 1));
                }
            }
            b = umax64(b, __shfl_xor_sync(0xFFFFFFFFu, b, 1));
            b = umax64(b, __shfl_xor_sync(0xFFFFFFFFu, b, 2));
            if ((lane & 3) == 0) atomicMax(&rowbest_s[mrow], b);
        }
    }

    // col-argmax (cols j0..j0+127 over rows i0..i0+127); sim[j][i] by symmetry.
    if (!diag) {
#pragma unroll
        for (int nt = 0; nt < 4; nt++) {
#pragma unroll
            for (int c = 0; c < 2; c++) {
                unsigned long long b = 0ULL;
#pragma unroll
                for (int mt = 0; mt < 4; mt++)
#pragma unroll
                    for (int h = 0; h < 2; h++) {
                        const __half2 hv = *reinterpret_cast<__half2*>(&acc[mt][nt][h]);
                        const float v = (c == 0) ? __low2float(hv) : __high2float(hv);
                        const int ig = i0 + wr * 64 + mt * 16 + qr + 8 * h;
                        b = umax64(b, packmax(v, ig));
                    }
                b = umax64(b, __shfl_xor_sync(0xFFFFFFFFu, b, 4));
                b = umax64(b, __shfl_xor_sync(0xFFFFFFFFu, b, 8));
                b = umax64(b, __shfl_xor_sync(0xFFFFFFFFu, b, 16));
                if (lane < 4)
                    atomicMax(&colbest_s[wc * 32 + nt * 8 + qc + c], b);
            }
        }
    }
    __syncthreads();
    if (tid < 128) {
        atomicMax(&g_best[i0 + tid], rowbest_s[tid]);
        if (!diag) atomicMax(&g_best[j0 + tid], colbest_s[tid]);
    }
}

// ---------------------------------------------------------------------------
// Kernel 3: d_an gather + weighted ratio sum (float4 vectorized, exact fp32)
// ---------------------------------------------------------------------------
__global__ void finalize_kernel(const float* __restrict__ x, float* out) {
    const int i = blockIdx.x;
    const unsigned jg = ~(unsigned)(g_best[i] & 0xFFFFFFFFULL);
    const float4* xi = reinterpret_cast<const float4*>(x + (size_t)i * DIM);
    const float4* xj = reinterpret_cast<const float4*>(x + (size_t)jg * DIM);

    float s = 0.0f;
    for (int d = threadIdx.x; d < DIM / 4; d += 256) {
        const float4 a = xi[d], b = xj[d];
        s += fabsf(a.x - b.x) + fabsf(a.y - b.y) + fabsf(a.z - b.z) + fabsf(a.w - b.w);
    }
#pragma unroll
    for (int o = 16; o > 0; o >>= 1)
        s += __shfl_xor_sync(0xFFFFFFFFu, s, o);

    __shared__ float sw[8];
    if ((threadIdx.x & 31) == 0) sw[threadIdx.x >> 5] = s;
    __syncthreads();
    if (threadIdx.x == 0) {
        float tot = 0.0f;
#pragma unroll
        for (int w = 0; w < 8; w++) tot += sw[w];
        const float dan = tot / (float)DIM;
        atomicAdd(out, 0.125f * g_dap[i] / (dan + 1e-7f));
    }
}

// ---------------------------------------------------------------------------
extern "C" void kernel_launch(void* const* d_in, const int* in_sizes, int n_in,
                              void* d_out, int out_size) {
    const float* x = (const float*)d_in[0];
    float* out = (float*)d_out;

    static bool attr_set = false;
    if (!attr_set) {
        cudaFuncSetAttribute(simgemm_kernel,
                             cudaFuncAttributeMaxDynamicSharedMemorySize, SMEM_BYTES);
        attr_set = true;
    }

    prep_kernel<<<NROWS / CS, 512>>>(x, out);
    simgemm_kernel<<<NPAIR, 256, SMEM_BYTES>>>();
    finalize_kernel<<<NROWS, 256>>>(x, out);
}